// round 1
// baseline (speedup 1.0000x reference)
#include <cuda_runtime.h>
#include <math.h>

#define H_DIM   1024
#define FF_DIM  4096
#define NEXP    8
#define NTOK    8192      // B*S = 4*2048
#define CAP     1024      // max(4, 8192/8)

// ---------------- scratch (device globals: no allocation allowed) ----------------
__device__ float d_Hres[(size_t)NTOK * FF_DIM];          // 128 MB
__device__ float d_Res [(size_t)NTOK * H_DIM];           // 32 MB
__device__ float d_Hexp[(size_t)NEXP * CAP * FF_DIM];    // 128 MB
__device__ float d_Eout[(size_t)NEXP * CAP * H_DIM];     // 32 MB
__device__ int   d_idx    [NTOK];
__device__ float d_gateval[NTOK];
__device__ int   d_pos    [NTOK];
__device__ int   d_slot   [NEXP * CAP];
__device__ float d_mesum  [NEXP];
__device__ int   d_count  [NEXP];

// ---------------- helpers ----------------
__device__ __forceinline__ float gelu_tanh(float x) {
    // matches jax.nn.gelu(approximate=True)
    const float k0 = 0.7978845608028654f;   // sqrt(2/pi)
    float x3 = x * x * x;
    return 0.5f * x * (1.0f + tanhf(k0 * (x + 0.044715f * x3)));
}

// ---------------- tiny init ----------------
__global__ void zero_kernel() {
    int t = threadIdx.x;
    if (t < NEXP) { d_mesum[t] = 0.0f; d_count[t] = 0; }
}

// ---------------- gating: one warp per token ----------------
__global__ void gate_kernel(const float* __restrict__ x, const float* __restrict__ wg) {
    int warp = threadIdx.x >> 5, lane = threadIdx.x & 31;
    int t = blockIdx.x * 8 + warp;
    const float* xt = x + (size_t)t * H_DIM;
    float acc[8] = {0,0,0,0,0,0,0,0};
    for (int h = lane; h < H_DIM; h += 32) {
        float v = xt[h];
        const float4 w0 = *(const float4*)(wg + (size_t)h * 8);
        const float4 w1 = *(const float4*)(wg + (size_t)h * 8 + 4);
        acc[0] += v * w0.x; acc[1] += v * w0.y; acc[2] += v * w0.z; acc[3] += v * w0.w;
        acc[4] += v * w1.x; acc[5] += v * w1.y; acc[6] += v * w1.z; acc[7] += v * w1.w;
    }
    #pragma unroll
    for (int o = 16; o > 0; o >>= 1)
        #pragma unroll
        for (int e = 0; e < 8; e++)
            acc[e] += __shfl_xor_sync(0xffffffffu, acc[e], o);
    if (lane == 0) {
        float m = acc[0]; int mi = 0;
        #pragma unroll
        for (int e = 1; e < 8; e++) if (acc[e] > m) { m = acc[e]; mi = e; }
        float ex[8], s = 0.0f;
        #pragma unroll
        for (int e = 0; e < 8; e++) { ex[e] = expf(acc[e] - m); s += ex[e]; }
        float inv = 1.0f / s;
        d_idx[t] = mi;
        d_gateval[t] = ex[mi] * inv;
        atomicAdd(&d_count[mi], 1);
        #pragma unroll
        for (int e = 0; e < 8; e++) atomicAdd(&d_mesum[e], ex[e] * inv);
    }
}

// ---------------- token-order prefix scan (capacity drop), single block ----------------
__global__ void scan_kernel() {
    __shared__ int cnt[1024][8];
    int tid = threadIdx.x;
    // init slot table
    for (int i = tid; i < NEXP * CAP; i += 1024) d_slot[i] = -1;
    int t0 = tid * 8;
    int te[8], loc[8] = {0,0,0,0,0,0,0,0};
    #pragma unroll
    for (int i = 0; i < 8; i++) { te[i] = d_idx[t0 + i]; loc[te[i]]++; }
    #pragma unroll
    for (int e = 0; e < 8; e++) cnt[tid][e] = loc[e];
    __syncthreads();
    for (int off = 1; off < 1024; off <<= 1) {
        int v[8];
        #pragma unroll
        for (int e = 0; e < 8; e++) v[e] = (tid >= off) ? cnt[tid - off][e] : 0;
        __syncthreads();
        #pragma unroll
        for (int e = 0; e < 8; e++) cnt[tid][e] += v[e];
        __syncthreads();
    }
    int run[8];
    #pragma unroll
    for (int e = 0; e < 8; e++) run[e] = cnt[tid][e] - loc[e];  // exclusive base
    #pragma unroll
    for (int i = 0; i < 8; i++) {
        int e = te[i];
        int p = run[e]++;
        d_pos[t0 + i] = p;
        if (p < CAP) d_slot[e * CAP + p] = t0 + i;
    }
}

// ---------------- 128x128x16 fp32 SGEMM, 8x8 microtile, optional gather + gelu ----------------
template<bool GELU, bool GATHER>
__global__ void __launch_bounds__(256, 2)
sgemm_kernel(const float* __restrict__ A, const float* __restrict__ Bm, float* __restrict__ C,
             int M, int N, int K,
             const int* __restrict__ rowidx,
             size_t strideA, size_t strideB, size_t strideC, int ridx_stride)
{
    const int BK = 16;
    __shared__ float As[BK][128];
    __shared__ float Bs[BK][128];
    int bz = blockIdx.z;
    const float* Ab = A + (size_t)bz * strideA;
    const float* Bb = Bm + (size_t)bz * strideB;
    float* Cb = C + (size_t)bz * strideC;
    const int* ridx = GATHER ? (rowidx + (size_t)bz * ridx_stride) : nullptr;
    int bm = blockIdx.y * 128, bn = blockIdx.x * 128;
    int tid = threadIdx.x;
    int tx = tid & 15, ty = tid >> 4;

    float acc[8][8];
    #pragma unroll
    for (int i = 0; i < 8; i++)
        #pragma unroll
        for (int j = 0; j < 8; j++) acc[i][j] = 0.0f;

    for (int k0 = 0; k0 < K; k0 += BK) {
        // load A tile: 128 rows x 16 cols, 512 float4, 2 per thread
        #pragma unroll
        for (int i = 0; i < 2; i++) {
            int f = tid + 256 * i;
            int r = f >> 2, c4 = (f & 3) * 4;
            float4 v = make_float4(0.f, 0.f, 0.f, 0.f);
            if (GATHER) {
                int g = ridx[bm + r];
                if (g >= 0) v = *(const float4*)(Ab + (size_t)g * K + k0 + c4);
            } else {
                v = *(const float4*)(Ab + (size_t)(bm + r) * K + k0 + c4);
            }
            As[c4 + 0][r] = v.x; As[c4 + 1][r] = v.y;
            As[c4 + 2][r] = v.z; As[c4 + 3][r] = v.w;
        }
        // load B tile: 16 rows x 128 cols
        #pragma unroll
        for (int i = 0; i < 2; i++) {
            int f = tid + 256 * i;
            int r = f >> 5, c4 = (f & 31) * 4;
            *(float4*)(&Bs[r][c4]) = *(const float4*)(Bb + (size_t)(k0 + r) * N + bn + c4);
        }
        __syncthreads();
        #pragma unroll
        for (int kk = 0; kk < BK; kk++) {
            float4 a0 = *(const float4*)(&As[kk][ty * 4]);
            float4 a1 = *(const float4*)(&As[kk][64 + ty * 4]);
            float4 b0 = *(const float4*)(&Bs[kk][tx * 4]);
            float4 b1 = *(const float4*)(&Bs[kk][64 + tx * 4]);
            float a[8] = {a0.x, a0.y, a0.z, a0.w, a1.x, a1.y, a1.z, a1.w};
            float b[8] = {b0.x, b0.y, b0.z, b0.w, b1.x, b1.y, b1.z, b1.w};
            #pragma unroll
            for (int i = 0; i < 8; i++)
                #pragma unroll
                for (int j = 0; j < 8; j++)
                    acc[i][j] += a[i] * b[j];
        }
        __syncthreads();
    }
    // epilogue
    #pragma unroll
    for (int i = 0; i < 8; i++) {
        int r = bm + ((i < 4) ? (ty * 4 + i) : (64 + ty * 4 + (i - 4)));
        float4 v0, v1;
        if (GELU) {
            v0 = make_float4(gelu_tanh(acc[i][0]), gelu_tanh(acc[i][1]),
                             gelu_tanh(acc[i][2]), gelu_tanh(acc[i][3]));
            v1 = make_float4(gelu_tanh(acc[i][4]), gelu_tanh(acc[i][5]),
                             gelu_tanh(acc[i][6]), gelu_tanh(acc[i][7]));
        } else {
            v0 = make_float4(acc[i][0], acc[i][1], acc[i][2], acc[i][3]);
            v1 = make_float4(acc[i][4], acc[i][5], acc[i][6], acc[i][7]);
        }
        *(float4*)(Cb + (size_t)r * N + bn + tx * 4)      = v0;
        *(float4*)(Cb + (size_t)r * N + bn + 64 + tx * 4) = v1;
    }
}

// ---------------- combine: out = g*Eout[e,p]*a0 + Res*a1 ----------------
__global__ void combine_kernel(const float* __restrict__ x,
                               const float* __restrict__ coef_w,
                               const float* __restrict__ coef_b,
                               float* __restrict__ out)
{
    int t = blockIdx.x;
    int tid = threadIdx.x, lane = tid & 31, warp = tid >> 5;
    const float* xt = x + (size_t)t * H_DIM;

    float p0 = 0.f, p1 = 0.f;
    for (int h = tid; h < H_DIM; h += 128) {
        float v = xt[h];
        p0 += v * coef_w[2 * h];
        p1 += v * coef_w[2 * h + 1];
    }
    #pragma unroll
    for (int o = 16; o > 0; o >>= 1) {
        p0 += __shfl_xor_sync(0xffffffffu, p0, o);
        p1 += __shfl_xor_sync(0xffffffffu, p1, o);
    }
    __shared__ float r0[4], r1[4], co[2];
    if (lane == 0) { r0[warp] = p0; r1[warp] = p1; }
    __syncthreads();
    if (tid == 0) {
        float c0 = r0[0] + r0[1] + r0[2] + r0[3] + coef_b[0];
        float c1 = r1[0] + r1[1] + r1[2] + r1[3] + coef_b[1];
        float m = fmaxf(c0, c1);
        float e0 = expf(c0 - m), e1 = expf(c1 - m);
        float inv = 1.0f / (e0 + e1);
        co[0] = e0 * inv; co[1] = e1 * inv;
    }
    __syncthreads();
    float a0 = co[0], a1 = co[1];

    int e = d_idx[t], p = d_pos[t];
    bool kept = (p < CAP);
    int pc = kept ? p : 0;
    float g = d_gateval[t];
    const float* eo = d_Eout + ((size_t)e * CAP + pc) * H_DIM;
    const float* rs = d_Res + (size_t)t * H_DIM;
    float* ot = out + (size_t)t * H_DIM;
    for (int h = tid; h < H_DIM; h += 128) {
        float moe = 0.0f;
        if (kept) moe = g * eo[h];
        ot[h] = moe * a0 + rs[h] * a1;
    }
}

// ---------------- aux outputs: l_aux + exp_counts ----------------
__global__ void aux_kernel(float* __restrict__ out) {
    const size_t BSH = (size_t)NTOK * H_DIM;
    if (threadIdx.x == 0) {
        float l = 0.0f;
        for (int e = 0; e < NEXP; e++)
            l += (d_mesum[e] / (float)NTOK) * ((float)d_count[e] / (float)NTOK);
        out[BSH] = l * (float)NEXP;
    }
    if (threadIdx.x < NEXP)
        out[BSH + 1 + threadIdx.x] = (float)d_count[threadIdx.x];
}

// ---------------- launch ----------------
extern "C" void kernel_launch(void* const* d_in, const int* in_sizes, int n_in,
                              void* d_out, int out_size) {
    const float* x   = (const float*)d_in[0];
    const float* wg  = (const float*)d_in[1];
    const float* w1  = (const float*)d_in[2];
    const float* w2  = (const float*)d_in[3];
    const float* rw1 = (const float*)d_in[4];
    const float* rw2 = (const float*)d_in[5];
    const float* cw  = (const float*)d_in[6];
    const float* cb  = (const float*)d_in[7];
    float* out = (float*)d_out;

    float *Hres, *Res, *Hexp, *Eout;
    int* slot;
    cudaGetSymbolAddress((void**)&Hres, d_Hres);
    cudaGetSymbolAddress((void**)&Res,  d_Res);
    cudaGetSymbolAddress((void**)&Hexp, d_Hexp);
    cudaGetSymbolAddress((void**)&Eout, d_Eout);
    cudaGetSymbolAddress((void**)&slot, d_slot);

    zero_kernel<<<1, 32>>>();
    gate_kernel<<<NTOK / 8, 256>>>(x, wg);
    scan_kernel<<<1, 1024>>>();

    // residual branch: Hres = gelu(x @ res_w1); Res = Hres @ res_w2
    sgemm_kernel<true,  false><<<dim3(FF_DIM / 128, NTOK / 128, 1), 256>>>(
        x, rw1, Hres, NTOK, FF_DIM, H_DIM, nullptr, 0, 0, 0, 0);
    sgemm_kernel<false, false><<<dim3(H_DIM / 128, NTOK / 128, 1), 256>>>(
        Hres, rw2, Res, NTOK, H_DIM, FF_DIM, nullptr, 0, 0, 0, 0);

    // expert branch: gather rows via slot table, batched over 8 experts (grid.z)
    sgemm_kernel<true,  true ><<<dim3(FF_DIM / 128, CAP / 128, NEXP), 256>>>(
        x, w1, Hexp, CAP, FF_DIM, H_DIM, slot,
        0, (size_t)H_DIM * FF_DIM, (size_t)CAP * FF_DIM, CAP);
    sgemm_kernel<false, false><<<dim3(H_DIM / 128, CAP / 128, NEXP), 256>>>(
        Hexp, w2, Eout, CAP, H_DIM, FF_DIM, nullptr,
        (size_t)CAP * FF_DIM, (size_t)FF_DIM * H_DIM, (size_t)CAP * H_DIM, 0);

    combine_kernel<<<NTOK, 128>>>(x, cw, cb, out);

    if (out_size >= NTOK * H_DIM + 1 + NEXP)
        aux_kernel<<<1, 32>>>(out);
}

// round 3
// speedup vs baseline: 2.6170x; 2.6170x over previous
#include <cuda_runtime.h>
#include <cuda_bf16.h>
#include <math.h>
#include <stdint.h>

#define H_DIM   1024
#define FF_DIM  4096
#define NEXP    8
#define NTOK    8192
#define CAP     1024

// ---------------- GEMM tile config ----------------
#define BM 128
#define BN 128
#define BKE 64                          // K elements per smem tile (128B rows)
#define TILE_HALF_BYTES (128 * BKE * 2) // 16 KB
#define AHI_OFF 0
#define ALO_OFF (TILE_HALF_BYTES)
#define BHI_OFF (2 * TILE_HALF_BYTES)
#define BLO_OFF (3 * TILE_HALF_BYTES)
#define STAGE_BYTES (4 * TILE_HALF_BYTES)  // 64 KB
#define NSTAGE 3
#define GSMEM_BYTES (NSTAGE * STAGE_BYTES + 1024)

// ---------------- scratch (device globals) ----------------
__device__ __nv_bfloat16 g_xhi [(size_t)NTOK * H_DIM];
__device__ __nv_bfloat16 g_xlo [(size_t)NTOK * H_DIM];
__device__ __nv_bfloat16 g_rw1t_hi[(size_t)FF_DIM * H_DIM];
__device__ __nv_bfloat16 g_rw1t_lo[(size_t)FF_DIM * H_DIM];
__device__ __nv_bfloat16 g_rw2t_hi[(size_t)H_DIM * FF_DIM];
__device__ __nv_bfloat16 g_rw2t_lo[(size_t)H_DIM * FF_DIM];
__device__ __nv_bfloat16 g_w1t_hi[(size_t)NEXP * FF_DIM * H_DIM];
__device__ __nv_bfloat16 g_w1t_lo[(size_t)NEXP * FF_DIM * H_DIM];
__device__ __nv_bfloat16 g_w2t_hi[(size_t)NEXP * H_DIM * FF_DIM];
__device__ __nv_bfloat16 g_w2t_lo[(size_t)NEXP * H_DIM * FF_DIM];
__device__ __nv_bfloat16 g_Hres_hi[(size_t)NTOK * FF_DIM];
__device__ __nv_bfloat16 g_Hres_lo[(size_t)NTOK * FF_DIM];
__device__ __nv_bfloat16 g_Hexp_hi[(size_t)NEXP * CAP * FF_DIM];
__device__ __nv_bfloat16 g_Hexp_lo[(size_t)NEXP * CAP * FF_DIM];
__device__ float d_Res [(size_t)NTOK * H_DIM];
__device__ float d_Eout[(size_t)NEXP * CAP * H_DIM];
__device__ int   d_idx    [NTOK];
__device__ float d_gateval[NTOK];
__device__ int   d_pos    [NTOK];
__device__ int   d_slot   [NEXP * CAP];
__device__ float d_mesum  [NEXP];
__device__ int   d_count  [NEXP];

// ---------------- helpers ----------------
__device__ __forceinline__ float gelu_tanh(float x) {
    const float k0 = 0.7978845608028654f;
    float x3 = x * x * x;
    return 0.5f * x * (1.0f + tanhf(k0 * (x + 0.044715f * x3)));
}

__device__ __forceinline__ uint32_t smem_u32(const void* p) {
    uint32_t a;
    asm("{ .reg .u64 t; cvta.to.shared.u64 t, %1; cvt.u32.u64 %0, t; }" : "=r"(a) : "l"(p));
    return a;
}

#define CP_A16(dst, src)   asm volatile("cp.async.cg.shared.global [%0], [%1], 16;\n" :: "r"(dst), "l"(src))
#define CP_A16_Z(dst, src) asm volatile("cp.async.cg.shared.global [%0], [%1], 16, 0;\n" :: "r"(dst), "l"(src))
#define CP_COMMIT()        asm volatile("cp.async.commit_group;\n" ::: "memory")
#define CP_WAIT1()         asm volatile("cp.async.wait_group 1;\n" ::: "memory")
#define CP_WAIT0()         asm volatile("cp.async.wait_group 0;\n" ::: "memory")

#define LDSM4(r0, r1, r2, r3, addr) \
    asm volatile("ldmatrix.sync.aligned.m8n8.x4.shared.b16 {%0,%1,%2,%3}, [%4];" \
                 : "=r"(r0), "=r"(r1), "=r"(r2), "=r"(r3) : "r"(addr))

#define MMA16816(d, a, b0, b1) \
    asm volatile("mma.sync.aligned.m16n8k16.row.col.f32.bf16.bf16.f32 " \
                 "{%0,%1,%2,%3},{%4,%5,%6,%7},{%8,%9},{%0,%1,%2,%3};" \
                 : "+f"((d)[0]), "+f"((d)[1]), "+f"((d)[2]), "+f"((d)[3]) \
                 : "r"((a)[0]), "r"((a)[1]), "r"((a)[2]), "r"((a)[3]), "r"(b0), "r"(b1))

// swizzle a (row,16B-chunk) offset inside a 128B-row tile (SW128-compatible)
__device__ __forceinline__ uint32_t swz(int row, int chunk) {
    return (uint32_t)(row * 128 + ((chunk ^ (row & 7)) << 4));
}

// ---------------- mma.sync GEMM: C[M,N] = A[M,K] @ Bt[N,K]^T (bf16x3 split) ----------------
template<bool OUTSPLIT, bool GATHER>
__global__ void __launch_bounds__(256, 1)
mma_gemm(const __nv_bfloat16* __restrict__ Ahi, const __nv_bfloat16* __restrict__ Alo,
         const __nv_bfloat16* __restrict__ Bhi, const __nv_bfloat16* __restrict__ Blo,
         __nv_bfloat16* __restrict__ Chi, __nv_bfloat16* __restrict__ Clo,
         float* __restrict__ Cf,
         int M, int N, int K,
         const int* __restrict__ slot,
         size_t sA, size_t sB, size_t sC, int slotStride)
{
    extern __shared__ char dsm[];
    const int tid  = threadIdx.x;
    const int wid  = tid >> 5, lane = tid & 31;
    const int z    = blockIdx.z;
    const int bm   = blockIdx.y * BM, bn = blockIdx.x * BN;
    const int wM   = (wid & 1) * 64;     // warp M offset (2 warps in M)
    const int wN   = (wid >> 1) * 32;    // warp N offset (4 warps in N)

    Ahi += (size_t)z * sA;  Alo += (size_t)z * sA;
    Bhi += (size_t)z * sB;  Blo += (size_t)z * sB;
    if (OUTSPLIT) { Chi += (size_t)z * sC; Clo += (size_t)z * sC; }
    else          { Cf  += (size_t)z * sC; }
    const int* slotp = GATHER ? (slot + (size_t)z * slotStride) : nullptr;

    const uint32_t sb = (smem_u32(dsm) + 1023u) & ~1023u;

    // ---- per-thread load maps: 8 A-chunks + 8 B-chunks (16B each) per stage ----
    uint32_t aOff[8]; const __nv_bfloat16* aSrc[8]; bool aOk[8];
    uint32_t bOff[8]; const __nv_bfloat16* bSrc[8];
    #pragma unroll
    for (int it = 0; it < 8; it++) {
        int ci = tid + 256 * it;                // 0..2047
        int half = ci >> 10, c = ci & 1023;     // 1024 chunks per half (128 rows x 8)
        int row = c >> 3, c16 = c & 7;
        aOff[it] = (half ? ALO_OFF : AHI_OFF) + swz(row, c16);
        int grow; bool ok = true;
        if (GATHER) { int g = slotp[bm + row]; ok = (g >= 0); grow = ok ? g : 0; }
        else        { grow = bm + row; }
        aOk[it]  = ok;
        aSrc[it] = (half ? Alo : Ahi) + (size_t)grow * K + c16 * 8;

        bOff[it] = (half ? BLO_OFF : BHI_OFF) + swz(row, c16);
        bSrc[it] = (half ? Blo : Bhi) + (size_t)(bn + row) * K + c16 * 8;
    }

    const int T = K / BKE;

    auto load_tile = [&](int stage, int k0) {
        uint32_t base = sb + stage * STAGE_BYTES;
        #pragma unroll
        for (int it = 0; it < 8; it++) {
            if (aOk[it]) { CP_A16(base + aOff[it], aSrc[it] + k0); }
            else         { CP_A16_Z(base + aOff[it], aSrc[it]); }
        }
        #pragma unroll
        for (int it = 0; it < 8; it++) {
            CP_A16(base + bOff[it], bSrc[it] + k0);
        }
        CP_COMMIT();
    };

    float acc[4][4][4];
    #pragma unroll
    for (int f = 0; f < 4; f++)
        #pragma unroll
        for (int nb = 0; nb < 4; nb++)
            #pragma unroll
            for (int q = 0; q < 4; q++) acc[f][nb][q] = 0.0f;

    load_tile(0, 0);
    load_tile(1, BKE);

    // precompute intra-warp ldmatrix address components
    const int aRowL = (lane & 15);               // + wM + f*16
    const int aChkL = (lane >> 4);               // + 2*kk
    const int bRowL = ((lane >> 4) << 3) + (lane & 7);   // + wN + h*16
    const int bChkL = ((lane >> 3) & 1);         // + 2*kk

    for (int i = 0; i < T; i++) {
        if (i >= T - 2) { CP_WAIT0(); } else { CP_WAIT1(); }
        __syncthreads();
        if (i + 2 < T) load_tile((i + 2) % NSTAGE, (i + 2) * BKE);

        uint32_t base = sb + (i % NSTAGE) * STAGE_BYTES;
        #pragma unroll
        for (int kk = 0; kk < 4; kk++) {
            uint32_t aH[4][4], aL[4][4], bH[4][2], bL[4][2];
            #pragma unroll
            for (int f = 0; f < 4; f++) {
                int row = wM + f * 16 + aRowL;
                int chk = 2 * kk + aChkL;
                uint32_t off = swz(row, chk);
                LDSM4(aH[f][0], aH[f][1], aH[f][2], aH[f][3], base + AHI_OFF + off);
                LDSM4(aL[f][0], aL[f][1], aL[f][2], aL[f][3], base + ALO_OFF + off);
            }
            #pragma unroll
            for (int h = 0; h < 2; h++) {
                int row = wN + h * 16 + bRowL;
                int chk = 2 * kk + bChkL;
                uint32_t off = swz(row, chk);
                uint32_t r0, r1, r2, r3;
                LDSM4(r0, r1, r2, r3, base + BHI_OFF + off);
                bH[2 * h][0] = r0; bH[2 * h][1] = r1;
                bH[2 * h + 1][0] = r2; bH[2 * h + 1][1] = r3;
                LDSM4(r0, r1, r2, r3, base + BLO_OFF + off);
                bL[2 * h][0] = r0; bL[2 * h][1] = r1;
                bL[2 * h + 1][0] = r2; bL[2 * h + 1][1] = r3;
            }
            #pragma unroll
            for (int f = 0; f < 4; f++)
                #pragma unroll
                for (int nb = 0; nb < 4; nb++) {
                    MMA16816(acc[f][nb], aH[f], bH[nb][0], bH[nb][1]);
                    MMA16816(acc[f][nb], aL[f], bH[nb][0], bH[nb][1]);
                    MMA16816(acc[f][nb], aH[f], bL[nb][0], bL[nb][1]);
                }
        }
        __syncthreads();
    }

    // ---- epilogue ----
    #pragma unroll
    for (int f = 0; f < 4; f++) {
        int r0 = bm + wM + f * 16 + (lane >> 2);
        #pragma unroll
        for (int nb = 0; nb < 4; nb++) {
            int col = bn + wN + nb * 8 + (lane & 3) * 2;
            float c0 = acc[f][nb][0], c1 = acc[f][nb][1];
            float c2 = acc[f][nb][2], c3 = acc[f][nb][3];
            if (OUTSPLIT) {
                c0 = gelu_tanh(c0); c1 = gelu_tanh(c1);
                c2 = gelu_tanh(c2); c3 = gelu_tanh(c3);
                __nv_bfloat16 h0 = __float2bfloat16(c0), h1 = __float2bfloat16(c1);
                __nv_bfloat16 h2 = __float2bfloat16(c2), h3 = __float2bfloat16(c3);
                __nv_bfloat16 l0 = __float2bfloat16(c0 - __bfloat162float(h0));
                __nv_bfloat16 l1 = __float2bfloat16(c1 - __bfloat162float(h1));
                __nv_bfloat16 l2 = __float2bfloat16(c2 - __bfloat162float(h2));
                __nv_bfloat16 l3 = __float2bfloat16(c3 - __bfloat162float(h3));
                __nv_bfloat162 hv0; hv0.x = h0; hv0.y = h1;
                __nv_bfloat162 hv1; hv1.x = h2; hv1.y = h3;
                __nv_bfloat162 lv0; lv0.x = l0; lv0.y = l1;
                __nv_bfloat162 lv1; lv1.x = l2; lv1.y = l3;
                *reinterpret_cast<__nv_bfloat162*>(Chi + (size_t)r0 * N + col)       = hv0;
                *reinterpret_cast<__nv_bfloat162*>(Chi + (size_t)(r0 + 8) * N + col) = hv1;
                *reinterpret_cast<__nv_bfloat162*>(Clo + (size_t)r0 * N + col)       = lv0;
                *reinterpret_cast<__nv_bfloat162*>(Clo + (size_t)(r0 + 8) * N + col) = lv1;
            } else {
                *reinterpret_cast<float2*>(Cf + (size_t)r0 * N + col)       = make_float2(c0, c1);
                *reinterpret_cast<float2*>(Cf + (size_t)(r0 + 8) * N + col) = make_float2(c2, c3);
            }
        }
    }
}

// ---------------- preprocessing kernels ----------------
__global__ void convert_split_kernel(const float4* __restrict__ src,
                                     __nv_bfloat16* __restrict__ hi,
                                     __nv_bfloat16* __restrict__ lo, int n4) {
    int i = blockIdx.x * blockDim.x + threadIdx.x;
    if (i >= n4) return;
    float4 v = src[i];
    float vv[4] = {v.x, v.y, v.z, v.w};
    __nv_bfloat162 h2[2], l2[2];
    #pragma unroll
    for (int j = 0; j < 4; j++) {
        __nv_bfloat16 h = __float2bfloat16(vv[j]);
        float rem = vv[j] - __bfloat162float(h);
        __nv_bfloat16 l = __float2bfloat16(rem);
        if (j & 1) { h2[j >> 1].y = h; l2[j >> 1].y = l; }
        else       { h2[j >> 1].x = h; l2[j >> 1].x = l; }
    }
    reinterpret_cast<__nv_bfloat162*>(hi)[2 * i]     = h2[0];
    reinterpret_cast<__nv_bfloat162*>(hi)[2 * i + 1] = h2[1];
    reinterpret_cast<__nv_bfloat162*>(lo)[2 * i]     = l2[0];
    reinterpret_cast<__nv_bfloat162*>(lo)[2 * i + 1] = l2[1];
}

// W [K,N] fp32 (batched by z) -> Thi/Tlo [N,K] bf16
__global__ void transpose_split_kernel(const float* __restrict__ W,
                                       __nv_bfloat16* __restrict__ Thi,
                                       __nv_bfloat16* __restrict__ Tlo,
                                       int K, int N) {
    __shared__ float t[32][33];
    int zz = blockIdx.z;
    W   += (size_t)zz * K * N;
    Thi += (size_t)zz * N * K;
    Tlo += (size_t)zz * N * K;
    int n0 = blockIdx.x * 32, k0 = blockIdx.y * 32;
    int tx = threadIdx.x, ty = threadIdx.y;
    #pragma unroll
    for (int j = 0; j < 4; j++)
        t[ty + 8 * j][tx] = W[(size_t)(k0 + ty + 8 * j) * N + n0 + tx];
    __syncthreads();
    #pragma unroll
    for (int j = 0; j < 4; j++) {
        float v = t[tx][ty + 8 * j];
        __nv_bfloat16 h = __float2bfloat16(v);
        float rem = v - __bfloat162float(h);
        __nv_bfloat16 l = __float2bfloat16(rem);
        size_t o = (size_t)(n0 + ty + 8 * j) * K + k0 + tx;
        Thi[o] = h;
        Tlo[o] = l;
    }
}

// ---------------- gating / scan / combine / aux ----------------
__global__ void zero_kernel() {
    int t = threadIdx.x;
    if (t < NEXP) { d_mesum[t] = 0.0f; d_count[t] = 0; }
}

__global__ void gate_kernel(const float* __restrict__ x, const float* __restrict__ wg) {
    int warp = threadIdx.x >> 5, lane = threadIdx.x & 31;
    int t = blockIdx.x * 8 + warp;
    const float* xt = x + (size_t)t * H_DIM;
    float acc[8] = {0,0,0,0,0,0,0,0};
    for (int h = lane; h < H_DIM; h += 32) {
        float v = xt[h];
        const float4 w0 = *(const float4*)(wg + (size_t)h * 8);
        const float4 w1 = *(const float4*)(wg + (size_t)h * 8 + 4);
        acc[0] += v * w0.x; acc[1] += v * w0.y; acc[2] += v * w0.z; acc[3] += v * w0.w;
        acc[4] += v * w1.x; acc[5] += v * w1.y; acc[6] += v * w1.z; acc[7] += v * w1.w;
    }
    #pragma unroll
    for (int o = 16; o > 0; o >>= 1)
        #pragma unroll
        for (int e = 0; e < 8; e++)
            acc[e] += __shfl_xor_sync(0xffffffffu, acc[e], o);
    if (lane == 0) {
        float m = acc[0]; int mi = 0;
        #pragma unroll
        for (int e = 1; e < 8; e++) if (acc[e] > m) { m = acc[e]; mi = e; }
        float ex[8], s = 0.0f;
        #pragma unroll
        for (int e = 0; e < 8; e++) { ex[e] = expf(acc[e] - m); s += ex[e]; }
        float inv = 1.0f / s;
        d_idx[t] = mi;
        d_gateval[t] = ex[mi] * inv;
        atomicAdd(&d_count[mi], 1);
        #pragma unroll
        for (int e = 0; e < 8; e++) atomicAdd(&d_mesum[e], ex[e] * inv);
    }
}

__global__ void scan_kernel() {
    __shared__ int cnt[1024][8];
    int tid = threadIdx.x;
    for (int i = tid; i < NEXP * CAP; i += 1024) d_slot[i] = -1;
    int t0 = tid * 8;
    int te[8], loc[8] = {0,0,0,0,0,0,0,0};
    #pragma unroll
    for (int i = 0; i < 8; i++) { te[i] = d_idx[t0 + i]; loc[te[i]]++; }
    #pragma unroll
    for (int e = 0; e < 8; e++) cnt[tid][e] = loc[e];
    __syncthreads();
    for (int off = 1; off < 1024; off <<= 1) {
        int v[8];
        #pragma unroll
        for (int e = 0; e < 8; e++) v[e] = (tid >= off) ? cnt[tid - off][e] : 0;
        __syncthreads();
        #pragma unroll
        for (int e = 0; e < 8; e++) cnt[tid][e] += v[e];
        __syncthreads();
    }
    int run[8];
    #pragma unroll
    for (int e = 0; e < 8; e++) run[e] = cnt[tid][e] - loc[e];
    #pragma unroll
    for (int i = 0; i < 8; i++) {
        int e = te[i];
        int p = run[e]++;
        d_pos[t0 + i] = p;
        if (p < CAP) d_slot[e * CAP + p] = t0 + i;
    }
}

__global__ void combine_kernel(const float* __restrict__ x,
                               const float* __restrict__ coef_w,
                               const float* __restrict__ coef_b,
                               float* __restrict__ out)
{
    int t = blockIdx.x;
    int tid = threadIdx.x, lane = tid & 31, warp = tid >> 5;
    const float* xt = x + (size_t)t * H_DIM;

    float p0 = 0.f, p1 = 0.f;
    for (int h = tid; h < H_DIM; h += 128) {
        float v = xt[h];
        p0 += v * coef_w[2 * h];
        p1 += v * coef_w[2 * h + 1];
    }
    #pragma unroll
    for (int o = 16; o > 0; o >>= 1) {
        p0 += __shfl_xor_sync(0xffffffffu, p0, o);
        p1 += __shfl_xor_sync(0xffffffffu, p1, o);
    }
    __shared__ float r0[4], r1[4], co[2];
    if (lane == 0) { r0[warp] = p0; r1[warp] = p1; }
    __syncthreads();
    if (tid == 0) {
        float c0 = r0[0] + r0[1] + r0[2] + r0[3] + coef_b[0];
        float c1 = r1[0] + r1[1] + r1[2] + r1[3] + coef_b[1];
        float m = fmaxf(c0, c1);
        float e0 = expf(c0 - m), e1 = expf(c1 - m);
        float inv = 1.0f / (e0 + e1);
        co[0] = e0 * inv; co[1] = e1 * inv;
    }
    __syncthreads();
    float a0 = co[0], a1 = co[1];

    int e = d_idx[t], p = d_pos[t];
    bool kept = (p < CAP);
    int pc = kept ? p : 0;
    float g = d_gateval[t];
    const float* eo = d_Eout + ((size_t)e * CAP + pc) * H_DIM;
    const float* rs = d_Res + (size_t)t * H_DIM;
    float* ot = out + (size_t)t * H_DIM;
    for (int h = tid; h < H_DIM; h += 128) {
        float moe = 0.0f;
        if (kept) moe = g * eo[h];
        ot[h] = moe * a0 + rs[h] * a1;
    }
}

__global__ void aux_kernel(float* __restrict__ out) {
    const size_t BSH = (size_t)NTOK * H_DIM;
    if (threadIdx.x == 0) {
        float l = 0.0f;
        for (int e = 0; e < NEXP; e++)
            l += (d_mesum[e] / (float)NTOK) * ((float)d_count[e] / (float)NTOK);
        out[BSH] = l * (float)NEXP;
    }
    if (threadIdx.x < NEXP)
        out[BSH + 1 + threadIdx.x] = (float)d_count[threadIdx.x];
}

// ---------------- launch ----------------
extern "C" void kernel_launch(void* const* d_in, const int* in_sizes, int n_in,
                              void* d_out, int out_size) {
    const float* x   = (const float*)d_in[0];
    const float* wg  = (const float*)d_in[1];
    const float* w1  = (const float*)d_in[2];
    const float* w2  = (const float*)d_in[3];
    const float* rw1 = (const float*)d_in[4];
    const float* rw2 = (const float*)d_in[5];
    const float* cw  = (const float*)d_in[6];
    const float* cb  = (const float*)d_in[7];
    float* out = (float*)d_out;

    __nv_bfloat16 *xhi, *xlo, *rw1h, *rw1l, *rw2h, *rw2l, *w1h, *w1l, *w2h, *w2l;
    __nv_bfloat16 *Hrh, *Hrl, *Heh, *Hel;
    float *Res, *Eout;
    int* slot;
    cudaGetSymbolAddress((void**)&xhi,  g_xhi);
    cudaGetSymbolAddress((void**)&xlo,  g_xlo);
    cudaGetSymbolAddress((void**)&rw1h, g_rw1t_hi);
    cudaGetSymbolAddress((void**)&rw1l, g_rw1t_lo);
    cudaGetSymbolAddress((void**)&rw2h, g_rw2t_hi);
    cudaGetSymbolAddress((void**)&rw2l, g_rw2t_lo);
    cudaGetSymbolAddress((void**)&w1h,  g_w1t_hi);
    cudaGetSymbolAddress((void**)&w1l,  g_w1t_lo);
    cudaGetSymbolAddress((void**)&w2h,  g_w2t_hi);
    cudaGetSymbolAddress((void**)&w2l,  g_w2t_lo);
    cudaGetSymbolAddress((void**)&Hrh,  g_Hres_hi);
    cudaGetSymbolAddress((void**)&Hrl,  g_Hres_lo);
    cudaGetSymbolAddress((void**)&Heh,  g_Hexp_hi);
    cudaGetSymbolAddress((void**)&Hel,  g_Hexp_lo);
    cudaGetSymbolAddress((void**)&Res,  d_Res);
    cudaGetSymbolAddress((void**)&Eout, d_Eout);
    cudaGetSymbolAddress((void**)&slot, d_slot);

    cudaFuncSetAttribute(mma_gemm<true,  false>, cudaFuncAttributeMaxDynamicSharedMemorySize, GSMEM_BYTES);
    cudaFuncSetAttribute(mma_gemm<false, false>, cudaFuncAttributeMaxDynamicSharedMemorySize, GSMEM_BYTES);
    cudaFuncSetAttribute(mma_gemm<true,  true >, cudaFuncAttributeMaxDynamicSharedMemorySize, GSMEM_BYTES);

    zero_kernel<<<1, 32>>>();
    gate_kernel<<<NTOK / 8, 256>>>(x, wg);
    scan_kernel<<<1, 1024>>>();

    {
        int n4 = NTOK * H_DIM / 4;
        convert_split_kernel<<<(n4 + 255) / 256, 256>>>((const float4*)x, xhi, xlo, n4);
    }
    transpose_split_kernel<<<dim3(FF_DIM / 32, H_DIM / 32, 1),    dim3(32, 8)>>>(rw1, rw1h, rw1l, H_DIM, FF_DIM);
    transpose_split_kernel<<<dim3(H_DIM / 32, FF_DIM / 32, 1),    dim3(32, 8)>>>(rw2, rw2h, rw2l, FF_DIM, H_DIM);
    transpose_split_kernel<<<dim3(FF_DIM / 32, H_DIM / 32, NEXP), dim3(32, 8)>>>(w1, w1h, w1l, H_DIM, FF_DIM);
    transpose_split_kernel<<<dim3(H_DIM / 32, FF_DIM / 32, NEXP), dim3(32, 8)>>>(w2, w2h, w2l, FF_DIM, H_DIM);

    // residual branch
    mma_gemm<true, false><<<dim3(FF_DIM / BN, NTOK / BM, 1), 256, GSMEM_BYTES>>>(
        xhi, xlo, rw1h, rw1l, Hrh, Hrl, nullptr,
        NTOK, FF_DIM, H_DIM, nullptr, 0, 0, 0, 0);
    mma_gemm<false, false><<<dim3(H_DIM / BN, NTOK / BM, 1), 256, GSMEM_BYTES>>>(
        Hrh, Hrl, rw2h, rw2l, nullptr, nullptr, Res,
        NTOK, H_DIM, FF_DIM, nullptr, 0, 0, 0, 0);

    // expert branch
    mma_gemm<true, true><<<dim3(FF_DIM / BN, CAP / BM, NEXP), 256, GSMEM_BYTES>>>(
        xhi, xlo, w1h, w1l, Heh, Hel, nullptr,
        CAP, FF_DIM, H_DIM, slot,
        0, (size_t)FF_DIM * H_DIM, (size_t)CAP * FF_DIM, CAP);
    mma_gemm<false, false><<<dim3(H_DIM / BN, CAP / BM, NEXP), 256, GSMEM_BYTES>>>(
        Heh, Hel, w2h, w2l, nullptr, nullptr, Eout,
        CAP, H_DIM, FF_DIM, nullptr,
        (size_t)CAP * FF_DIM, (size_t)H_DIM * FF_DIM, (size_t)CAP * H_DIM, 0);

    combine_kernel<<<NTOK, 128>>>(x, cw, cb, out);

    if (out_size >= NTOK * H_DIM + 1 + NEXP)
        aux_kernel<<<1, 32>>>(out);
}